// round 9
// baseline (speedup 1.0000x reference)
#include <cuda_runtime.h>
#include <math.h>

#define BS_   2
#define S_    2048
#define D_    2048
#define DOWN_ 512
#define UP_   1024
#define H_    16
#define RD_   32
#define MROWS (BS_*S_)

#define INVSCALE (1.0f/16.970562748477139f)

__device__ float g_ckv[MROWS*DOWN_];
__device__ float g_cq [MROWS*DOWN_];
__device__ float g_krl[MROWS*RD_];
__device__ float g_kc [MROWS*UP_];
__device__ float g_vc [MROWS*UP_];
__device__ float g_qc [MROWS*UP_];
__device__ float g_qr [MROWS*(RD_*H_)];
__device__ float g_ao [MROWS*UP_];
__device__ float g_sc [(size_t)BS_*H_*S_*S_];   // 512 MB scores

// ---- GEMM: C[M,N] = A[M,K] @ B[N,K]^T + bias ----
__global__ void __launch_bounds__(256) gemm_bias(
    const float* __restrict__ A, const float* __restrict__ Bw,
    const float* __restrict__ bias, float* __restrict__ C,
    int M, int N, int K)
{
    __shared__ float As[128][17];
    __shared__ float Bs[64][17];
    const int tid = threadIdx.x;
    const int ty = tid >> 3, tx = tid & 7;
    const int rowBase = blockIdx.y * 128, colBase = blockIdx.x * 64;
    float acc[4][8];
    #pragma unroll
    for (int i = 0; i < 4; i++)
        #pragma unroll
        for (int j = 0; j < 8; j++) acc[i][j] = 0.f;

    for (int k0 = 0; k0 < K; k0 += 16) {
        #pragma unroll
        for (int i = 0; i < 8; i++) {
            int lin = tid + i*256, r = lin >> 4, c = lin & 15;
            As[r][c] = A[(size_t)(rowBase + r)*K + k0 + c];
        }
        #pragma unroll
        for (int i = 0; i < 4; i++) {
            int lin = tid + i*256, r = lin >> 4, c = lin & 15;
            int gr = colBase + r;
            Bs[r][c] = (gr < N) ? Bw[(size_t)gr*K + k0 + c] : 0.f;
        }
        __syncthreads();
        #pragma unroll
        for (int kk = 0; kk < 16; kk++) {
            float a[4], b[8];
            #pragma unroll
            for (int i = 0; i < 4; i++) a[i] = As[ty*4 + i][kk];
            #pragma unroll
            for (int j = 0; j < 8; j++) b[j] = Bs[tx + 8*j][kk];
            #pragma unroll
            for (int i = 0; i < 4; i++)
                #pragma unroll
                for (int j = 0; j < 8; j++)
                    acc[i][j] = fmaf(a[i], b[j], acc[i][j]);
        }
        __syncthreads();
    }
    #pragma unroll
    for (int i = 0; i < 4; i++) {
        int r = rowBase + ty*4 + i;
        #pragma unroll
        for (int j = 0; j < 8; j++) {
            int cN = colBase + tx + 8*j;
            if (cN < N) C[(size_t)r*N + cN] = acc[i][j] + bias[cN];
        }
    }
}

// ---- RoPE in place, head_dim 32, NEGATED angle (theta -> -theta) ----
__global__ void rope_kernel(float* __restrict__ x, int nheads, int rowStride)
{
    int row = blockIdx.x;
    int pos = row & (S_ - 1);
    int t = threadIdx.x;
    if (t >= nheads*16) return;
    int hh = t >> 4, j = t & 15;
    float* p = x + (size_t)row*rowStride + hh*32;
    double lf = -(double)j * (log(10000.0) / 16.0);
    float inv_freq = (float)exp(lf);
    float theta = (float)pos * inv_freq;
    float c, sn;
    sincosf(theta, &c, &sn);
    float x1 = p[j], x2 = p[j + 16];
    p[j]      = x1*c + x2*sn;    // negated-angle rotation
    p[j + 16] = x2*c - x1*sn;
}

// ---- scores = (Q @ K^T) masked, * INVSCALE ----
__global__ void __launch_bounds__(256) score_kernel(
    const float* __restrict__ qc, const float* __restrict__ qrr,
    const float* __restrict__ kc, const float* __restrict__ krr,
    const int* __restrict__ mask, float* __restrict__ scores)
{
    extern __shared__ float sm[];
    float* Qs = sm;            // [64][97]
    float* Ks = sm + 64*97;    // [64][97]
    const int tid = threadIdx.x;
    const int qb = blockIdx.x, kb = blockIdx.y;
    const int b = blockIdx.z >> 4, h = blockIdx.z & 15;
    const int q0 = qb*64, k0 = kb*64;

    for (int idx = tid; idx < 64*96; idx += 256) {
        int r = idx / 96, c = idx - r*96;
        size_t grow = (size_t)b*S_ + q0 + r;
        Qs[r*97 + c] = (c < 64) ? qc[grow*UP_ + h*64 + c]
                                : qrr[grow*(RD_*H_) + h*32 + (c - 64)];
    }
    for (int idx = tid; idx < 64*96; idx += 256) {
        int r = idx / 96, c = idx - r*96;
        size_t grow = (size_t)b*S_ + k0 + r;
        Ks[r*97 + c] = (c < 64) ? kc[grow*UP_ + h*64 + c]
                                : krr[grow*RD_ + (c - 64)];
    }
    __syncthreads();

    const int ty = tid >> 4, tx = tid & 15;
    float acc[4][4];
    #pragma unroll
    for (int i = 0; i < 4; i++)
        #pragma unroll
        for (int j = 0; j < 4; j++) acc[i][j] = 0.f;

    #pragma unroll 4
    for (int kk = 0; kk < 96; kk++) {
        float a[4], bb[4];
        #pragma unroll
        for (int i = 0; i < 4; i++) a[i] = Qs[(ty*4 + i)*97 + kk];
        #pragma unroll
        for (int j = 0; j < 4; j++) bb[j] = Ks[(tx*4 + j)*97 + kk];
        #pragma unroll
        for (int i = 0; i < 4; i++)
            #pragma unroll
            for (int j = 0; j < 4; j++)
                acc[i][j] = fmaf(a[i], bb[j], acc[i][j]);
    }

    float* srow = scores + (size_t)(b*H_ + h)*S_*S_;
    #pragma unroll
    for (int i = 0; i < 4; i++) {
        int q = q0 + ty*4 + i;
        #pragma unroll
        for (int j = 0; j < 4; j++) {
            int k = k0 + tx*4 + j;
            float v = (mask[(size_t)q*S_ + k] == 0) ? -1e9f : acc[i][j];
            srow[(size_t)q*S_ + k] = v * INVSCALE;
        }
    }
}

// ---- row softmax, in place ----
__global__ void __launch_bounds__(256) softmax_kernel(float* __restrict__ scores)
{
    const int q = blockIdx.x, h = blockIdx.y, b = blockIdx.z;
    float* row = scores + ((size_t)(b*H_ + h)*S_ + q)*S_;
    __shared__ float red[256];
    const int tid = threadIdx.x;

    float mx = -1e30f;
    for (int k = tid; k < S_; k += 256) mx = fmaxf(mx, row[k]);
    red[tid] = mx; __syncthreads();
    for (int s = 128; s > 0; s >>= 1) {
        if (tid < s) red[tid] = fmaxf(red[tid], red[tid + s]);
        __syncthreads();
    }
    mx = red[0]; __syncthreads();

    float sum = 0.f;
    for (int k = tid; k < S_; k += 256) {
        float e = __expf(row[k] - mx);
        row[k] = e; sum += e;
    }
    red[tid] = sum; __syncthreads();
    for (int s = 128; s > 0; s >>= 1) {
        if (tid < s) red[tid] += red[tid + s];
        __syncthreads();
    }
    float inv = 1.f / red[0];
    for (int k = tid; k < S_; k += 256) row[k] *= inv;
}

// ---- O = P @ V ----
__global__ void __launch_bounds__(256) pv_kernel(
    const float* __restrict__ scores, const float* __restrict__ vc,
    float* __restrict__ ao)
{
    __shared__ float Ps[64][65];
    __shared__ float Vs[64][65];
    const int qb = blockIdx.x, h = blockIdx.y, b = blockIdx.z;
    const int q0 = qb*64;
    const int tid = threadIdx.x;
    const int ty = tid >> 4, tx = tid & 15;
    const float* srow = scores + (size_t)(b*H_ + h)*S_*S_;

    float acc[4][4];
    #pragma unroll
    for (int i = 0; i < 4; i++)
        #pragma unroll
        for (int j = 0; j < 4; j++) acc[i][j] = 0.f;

    for (int k0 = 0; k0 <= q0; k0 += 64) {   // probs beyond diagonal are exactly 0
        for (int idx = tid; idx < 4096; idx += 256) {
            int r = idx >> 6, c = idx & 63;
            Ps[r][c] = srow[(size_t)(q0 + r)*S_ + k0 + c];
            Vs[r][c] = vc[(size_t)(b*S_ + k0 + r)*UP_ + h*64 + c];
        }
        __syncthreads();
        #pragma unroll 4
        for (int kk = 0; kk < 64; kk++) {
            float p[4], v[4];
            #pragma unroll
            for (int i = 0; i < 4; i++) p[i] = Ps[ty*4 + i][kk];
            #pragma unroll
            for (int j = 0; j < 4; j++) v[j] = Vs[kk][tx*4 + j];
            #pragma unroll
            for (int i = 0; i < 4; i++)
                #pragma unroll
                for (int j = 0; j < 4; j++)
                    acc[i][j] = fmaf(p[i], v[j], acc[i][j]);
        }
        __syncthreads();
    }
    #pragma unroll
    for (int i = 0; i < 4; i++)
        #pragma unroll
        for (int j = 0; j < 4; j++)
            ao[(size_t)(b*S_ + q0 + ty*4 + i)*UP_ + h*64 + tx*4 + j] = acc[i][j];
}

extern "C" void kernel_launch(void* const* d_in, const int* in_sizes, int n_in,
                              void* d_out, int out_size)
{
    const float* h    = (const float*)d_in[0];
    const int*   mask = (const int*)  d_in[1];
    const float* Wdkv = (const float*)d_in[2];  const float* bdkv = (const float*)d_in[3];
    const float* Wuk  = (const float*)d_in[4];  const float* buk  = (const float*)d_in[5];
    const float* Wuv  = (const float*)d_in[6];  const float* buv  = (const float*)d_in[7];
    const float* Wdq  = (const float*)d_in[8];  const float* bdq  = (const float*)d_in[9];
    const float* Wuq  = (const float*)d_in[10]; const float* buq  = (const float*)d_in[11];
    const float* Wqr  = (const float*)d_in[12]; const float* bqr  = (const float*)d_in[13];
    const float* Wkr  = (const float*)d_in[14]; const float* bkr  = (const float*)d_in[15];
    const float* Wfc  = (const float*)d_in[16]; const float* bfc  = (const float*)d_in[17];
    float* out = (float*)d_out;

    float *ckv, *cq, *krl, *kc, *vc, *qc, *qr, *ao, *sc;
    cudaGetSymbolAddress((void**)&ckv, g_ckv);
    cudaGetSymbolAddress((void**)&cq,  g_cq);
    cudaGetSymbolAddress((void**)&krl, g_krl);
    cudaGetSymbolAddress((void**)&kc,  g_kc);
    cudaGetSymbolAddress((void**)&vc,  g_vc);
    cudaGetSymbolAddress((void**)&qc,  g_qc);
    cudaGetSymbolAddress((void**)&qr,  g_qr);
    cudaGetSymbolAddress((void**)&ao,  g_ao);
    cudaGetSymbolAddress((void**)&sc,  g_sc);

    const int SC_SMEM = 2*64*97*(int)sizeof(float);   // 49664 B
    cudaFuncSetAttribute(score_kernel,
                         cudaFuncAttributeMaxDynamicSharedMemorySize, SC_SMEM);

    gemm_bias<<<dim3(8, 32), 256>>>(h,   Wdkv, bdkv, ckv, MROWS, DOWN_, D_);
    gemm_bias<<<dim3(8, 32), 256>>>(h,   Wdq,  bdq,  cq,  MROWS, DOWN_, D_);
    gemm_bias<<<dim3(1, 32), 256>>>(h,   Wkr,  bkr,  krl, MROWS, RD_,   D_);
    gemm_bias<<<dim3(16, 32), 256>>>(ckv, Wuk, buk, kc, MROWS, UP_,    DOWN_);
    gemm_bias<<<dim3(16, 32), 256>>>(ckv, Wuv, buv, vc, MROWS, UP_,    DOWN_);
    gemm_bias<<<dim3(16, 32), 256>>>(cq,  Wuq, buq, qc, MROWS, UP_,    DOWN_);
    gemm_bias<<<dim3(8, 32),  256>>>(cq,  Wqr, bqr, qr, MROWS, RD_*H_, DOWN_);

    rope_kernel<<<MROWS, 256>>>(qr,  H_, RD_*H_);
    rope_kernel<<<MROWS, 32>>>(krl, 1,  RD_);

    score_kernel<<<dim3(32, 32, 32), 256, SC_SMEM>>>(qc, qr, kc, krl, mask, sc);
    softmax_kernel<<<dim3(S_, H_, BS_), 256>>>(sc);
    pv_kernel<<<dim3(32, H_, BS_), 256>>>(sc, vc, ao);

    gemm_bias<<<dim3(32, 32), 256>>>(ao, Wfc, bfc, out, MROWS, D_, UP_);
}

// round 10
// speedup vs baseline: 1.3897x; 1.3897x over previous
#include <cuda_runtime.h>
#include <math.h>

#define BS_   2
#define S_    2048
#define D_    2048
#define DOWN_ 512
#define UP_   1024
#define H_    16
#define RD_   32
#define MROWS (BS_*S_)

#define INVSCALE (1.0f/16.970562748477139f)

__device__ float g_ckv[MROWS*DOWN_];
__device__ float g_cq [MROWS*DOWN_];
__device__ float g_krl[MROWS*RD_];
__device__ float g_kc [MROWS*UP_];
__device__ float g_vc [MROWS*UP_];
__device__ float g_qc [MROWS*UP_];
__device__ float g_qr [MROWS*(RD_*H_)];
__device__ float g_ao [MROWS*UP_];

// ---- big-tile GEMM: C[M,N] = A[M,K] @ B[N,K]^T + bias ----
// 128x128 tile, BK=16, 256 threads, 8x8 micro-tile (4+4 split), double-buffered.
// Requires M%128==0, N%128==0, K%16==0.
__global__ void __launch_bounds__(256) gemm128(
    const float* __restrict__ A, const float* __restrict__ Bw,
    const float* __restrict__ bias, float* __restrict__ C,
    int M, int N, int K)
{
    __shared__ float As[2][16][132];
    __shared__ float Bs[2][16][132];
    const int tid = threadIdx.x;
    const int ty = tid >> 4, tx = tid & 15;
    const int rowBase = blockIdx.y*128, colBase = blockIdx.x*128;
    const float* Ag = A  + (size_t)rowBase*K;
    const float* Bg = Bw + (size_t)colBase*K;

    float acc[8][8];
    #pragma unroll
    for (int i = 0; i < 8; i++)
        #pragma unroll
        for (int j = 0; j < 8; j++) acc[i][j] = 0.f;

    const int f0 = tid*2;

    // preload stage 0
    {
        #pragma unroll
        for (int i = 0; i < 2; i++) {
            int f = f0 + i;                 // 0..511
            int row = f >> 2, kq = (f & 3)*4;
            float4 va = *(const float4*)(Ag + (size_t)row*K + kq);
            As[0][kq+0][row]=va.x; As[0][kq+1][row]=va.y;
            As[0][kq+2][row]=va.z; As[0][kq+3][row]=va.w;
            float4 vb = *(const float4*)(Bg + (size_t)row*K + kq);
            Bs[0][kq+0][row]=vb.x; Bs[0][kq+1][row]=vb.y;
            Bs[0][kq+2][row]=vb.z; Bs[0][kq+3][row]=vb.w;
        }
    }
    __syncthreads();

    const int nK = K >> 4;
    for (int t = 0; t < nK; t++) {
        const int cur = t & 1;
        if (t + 1 < nK) {
            const int nxt = cur ^ 1;
            const int k0 = (t + 1) << 4;
            #pragma unroll
            for (int i = 0; i < 2; i++) {
                int f = f0 + i;
                int row = f >> 2, kq = (f & 3)*4;
                float4 va = *(const float4*)(Ag + (size_t)row*K + k0 + kq);
                As[nxt][kq+0][row]=va.x; As[nxt][kq+1][row]=va.y;
                As[nxt][kq+2][row]=va.z; As[nxt][kq+3][row]=va.w;
                float4 vb = *(const float4*)(Bg + (size_t)row*K + k0 + kq);
                Bs[nxt][kq+0][row]=vb.x; Bs[nxt][kq+1][row]=vb.y;
                Bs[nxt][kq+2][row]=vb.z; Bs[nxt][kq+3][row]=vb.w;
            }
        }
        #pragma unroll
        for (int kk = 0; kk < 16; kk++) {
            float4 a0 = *(const float4*)&As[cur][kk][ty*4];
            float4 a1 = *(const float4*)&As[cur][kk][64 + ty*4];
            float4 b0 = *(const float4*)&Bs[cur][kk][tx*4];
            float4 b1 = *(const float4*)&Bs[cur][kk][64 + tx*4];
            float a[8] = {a0.x,a0.y,a0.z,a0.w, a1.x,a1.y,a1.z,a1.w};
            float b[8] = {b0.x,b0.y,b0.z,b0.w, b1.x,b1.y,b1.z,b1.w};
            #pragma unroll
            for (int i = 0; i < 8; i++)
                #pragma unroll
                for (int j = 0; j < 8; j++)
                    acc[i][j] = fmaf(a[i], b[j], acc[i][j]);
        }
        __syncthreads();
    }

    // epilogue: vectorized stores, cols tx*4.. and 64+tx*4.. are contiguous x4
    const int c0 = colBase + tx*4, c1 = colBase + 64 + tx*4;
    float4 bv0 = *(const float4*)&bias[c0];
    float4 bv1 = *(const float4*)&bias[c1];
    #pragma unroll
    for (int i = 0; i < 8; i++) {
        int r = rowBase + ((i < 4) ? (ty*4 + i) : (64 + ty*4 + (i - 4)));
        float4 v0 = {acc[i][0]+bv0.x, acc[i][1]+bv0.y, acc[i][2]+bv0.z, acc[i][3]+bv0.w};
        float4 v1 = {acc[i][4]+bv1.x, acc[i][5]+bv1.y, acc[i][6]+bv1.z, acc[i][7]+bv1.w};
        *(float4*)&C[(size_t)r*N + c0] = v0;
        *(float4*)&C[(size_t)r*N + c1] = v1;
    }
}

// ---- small-N GEMM (for Wkr, N=32): original 128x64 kernel ----
__global__ void __launch_bounds__(256) gemm_bias(
    const float* __restrict__ A, const float* __restrict__ Bw,
    const float* __restrict__ bias, float* __restrict__ C,
    int M, int N, int K)
{
    __shared__ float As[128][17];
    __shared__ float Bs[64][17];
    const int tid = threadIdx.x;
    const int ty = tid >> 3, tx = tid & 7;
    const int rowBase = blockIdx.y * 128, colBase = blockIdx.x * 64;
    float acc[4][8];
    #pragma unroll
    for (int i = 0; i < 4; i++)
        #pragma unroll
        for (int j = 0; j < 8; j++) acc[i][j] = 0.f;

    for (int k0 = 0; k0 < K; k0 += 16) {
        #pragma unroll
        for (int i = 0; i < 8; i++) {
            int lin = tid + i*256, r = lin >> 4, c = lin & 15;
            As[r][c] = A[(size_t)(rowBase + r)*K + k0 + c];
        }
        #pragma unroll
        for (int i = 0; i < 4; i++) {
            int lin = tid + i*256, r = lin >> 4, c = lin & 15;
            int gr = colBase + r;
            Bs[r][c] = (gr < N) ? Bw[(size_t)gr*K + k0 + c] : 0.f;
        }
        __syncthreads();
        #pragma unroll
        for (int kk = 0; kk < 16; kk++) {
            float a[4], b[8];
            #pragma unroll
            for (int i = 0; i < 4; i++) a[i] = As[ty*4 + i][kk];
            #pragma unroll
            for (int j = 0; j < 8; j++) b[j] = Bs[tx + 8*j][kk];
            #pragma unroll
            for (int i = 0; i < 4; i++)
                #pragma unroll
                for (int j = 0; j < 8; j++)
                    acc[i][j] = fmaf(a[i], b[j], acc[i][j]);
        }
        __syncthreads();
    }
    #pragma unroll
    for (int i = 0; i < 4; i++) {
        int r = rowBase + ty*4 + i;
        #pragma unroll
        for (int j = 0; j < 8; j++) {
            int cN = colBase + tx + 8*j;
            if (cN < N) C[(size_t)r*N + cN] = acc[i][j] + bias[cN];
        }
    }
}

// ---- RoPE in place, head_dim 32, NEGATED angle (matches reference) ----
__global__ void rope_kernel(float* __restrict__ x, int nheads, int rowStride)
{
    int row = blockIdx.x;
    int pos = row & (S_ - 1);
    int t = threadIdx.x;
    if (t >= nheads*16) return;
    int hh = t >> 4, j = t & 15;
    float* p = x + (size_t)row*rowStride + hh*32;
    double lf = -(double)j * (log(10000.0) / 16.0);
    float inv_freq = (float)exp(lf);
    float theta = (float)pos * inv_freq;
    float c, sn;
    sincosf(theta, &c, &sn);
    float x1 = p[j], x2 = p[j + 16];
    p[j]      = x1*c + x2*sn;
    p[j + 16] = x2*c - x1*sn;
}

// ---- Flash attention (causal), fp32 — numerically validated in rounds 1-3 ----
__global__ void __launch_bounds__(128) attn_kernel(
    const float* __restrict__ qc, const float* __restrict__ qrr,
    const float* __restrict__ kc, const float* __restrict__ krr,
    const float* __restrict__ vc, float* __restrict__ out)
{
    extern __shared__ float smf[];
    float* Qs = smf;               // [64][97]
    float* Ks = smf + 64*97;       // [64][97], reused for P
    float* Vs = smf + 2*64*97;     // [64][65]

    const int tid = threadIdx.x;
    const int ty  = tid >> 3;   // 0..15
    const int tx  = tid & 7;    // 0..7
    const int qb = blockIdx.x, h = blockIdx.y, b = blockIdx.z;
    const int qs = qb * 64;
    const int rowOff = b * S_;

    for (int idx = tid; idx < 64*96; idx += 128) {
        int r = idx / 96, c = idx - r*96;
        int grow = rowOff + qs + r;
        Qs[r*97 + c] = (c < 64) ? qc[(size_t)grow*UP_ + h*64 + c]
                                : qrr[(size_t)grow*(RD_*H_) + h*32 + (c - 64)];
    }

    float m[4], l[4], o[4][8];
    #pragma unroll
    for (int i = 0; i < 4; i++) {
        m[i] = -1e30f; l[i] = 0.f;
        #pragma unroll
        for (int j = 0; j < 8; j++) o[i][j] = 0.f;
    }

    for (int kb = 0; kb <= qs; kb += 64) {
        __syncthreads();
        for (int idx = tid; idx < 64*96; idx += 128) {
            int r = idx / 96, c = idx - r*96;
            int grow = rowOff + kb + r;
            Ks[r*97 + c] = (c < 64) ? kc[(size_t)grow*UP_ + h*64 + c]
                                    : krr[(size_t)grow*RD_ + (c - 64)];
        }
        for (int idx = tid; idx < 64*64; idx += 128) {
            int r = idx >> 6, c = idx & 63;
            Vs[r*65 + c] = vc[(size_t)(rowOff + kb + r)*UP_ + h*64 + c];
        }
        __syncthreads();

        float s[4][8];
        #pragma unroll
        for (int i = 0; i < 4; i++)
            #pragma unroll
            for (int j = 0; j < 8; j++) s[i][j] = 0.f;

        #pragma unroll 4
        for (int kk = 0; kk < 96; kk++) {
            float a[4], bb[8];
            #pragma unroll
            for (int i = 0; i < 4; i++) a[i] = Qs[(ty*4 + i)*97 + kk];
            #pragma unroll
            for (int j = 0; j < 8; j++) bb[j] = Ks[(tx + 8*j)*97 + kk];
            #pragma unroll
            for (int i = 0; i < 4; i++)
                #pragma unroll
                for (int j = 0; j < 8; j++)
                    s[i][j] = fmaf(a[i], bb[j], s[i][j]);
        }

        const bool maskBlk = (kb == qs);
        #pragma unroll
        for (int i = 0; i < 4; i++)
            #pragma unroll
            for (int j = 0; j < 8; j++) {
                float v = s[i][j] * INVSCALE;
                if (maskBlk && (kb + tx + 8*j > qs + ty*4 + i)) v = -1e30f;
                s[i][j] = v;
            }

        #pragma unroll
        for (int i = 0; i < 4; i++) {
            float rm = s[i][0];
            #pragma unroll
            for (int j = 1; j < 8; j++) rm = fmaxf(rm, s[i][j]);
            rm = fmaxf(rm, __shfl_xor_sync(0xffffffffu, rm, 1));
            rm = fmaxf(rm, __shfl_xor_sync(0xffffffffu, rm, 2));
            rm = fmaxf(rm, __shfl_xor_sync(0xffffffffu, rm, 4));
            float mn = fmaxf(m[i], rm);
            float corr = __expf(m[i] - mn);
            l[i] *= corr;
            #pragma unroll
            for (int j = 0; j < 8; j++) o[i][j] *= corr;
            float rs = 0.f;
            #pragma unroll
            for (int j = 0; j < 8; j++) {
                float p = __expf(s[i][j] - mn);
                s[i][j] = p; rs += p;
            }
            rs += __shfl_xor_sync(0xffffffffu, rs, 1);
            rs += __shfl_xor_sync(0xffffffffu, rs, 2);
            rs += __shfl_xor_sync(0xffffffffu, rs, 4);
            l[i] += rs; m[i] = mn;
        }

        __syncthreads();
        #pragma unroll
        for (int i = 0; i < 4; i++)
            #pragma unroll
            for (int j = 0; j < 8; j++)
                Ks[(ty*4 + i)*97 + tx + 8*j] = s[i][j];
        __syncthreads();

        #pragma unroll 4
        for (int k = 0; k < 64; k++) {
            float p[4], vv[8];
            #pragma unroll
            for (int i = 0; i < 4; i++) p[i] = Ks[(ty*4 + i)*97 + k];
            #pragma unroll
            for (int j = 0; j < 8; j++) vv[j] = Vs[k*65 + tx + 8*j];
            #pragma unroll
            for (int i = 0; i < 4; i++)
                #pragma unroll
                for (int j = 0; j < 8; j++)
                    o[i][j] = fmaf(p[i], vv[j], o[i][j]);
        }
    }

    #pragma unroll
    for (int i = 0; i < 4; i++) {
        float inv = 1.f / l[i];
        int grow = rowOff + qs + ty*4 + i;
        #pragma unroll
        for (int j = 0; j < 8; j++)
            out[(size_t)grow*UP_ + h*64 + tx + 8*j] = o[i][j] * inv;
    }
}

extern "C" void kernel_launch(void* const* d_in, const int* in_sizes, int n_in,
                              void* d_out, int out_size)
{
    const float* h    = (const float*)d_in[0];
    const float* Wdkv = (const float*)d_in[2];  const float* bdkv = (const float*)d_in[3];
    const float* Wuk  = (const float*)d_in[4];  const float* buk  = (const float*)d_in[5];
    const float* Wuv  = (const float*)d_in[6];  const float* buv  = (const float*)d_in[7];
    const float* Wdq  = (const float*)d_in[8];  const float* bdq  = (const float*)d_in[9];
    const float* Wuq  = (const float*)d_in[10]; const float* buq  = (const float*)d_in[11];
    const float* Wqr  = (const float*)d_in[12]; const float* bqr  = (const float*)d_in[13];
    const float* Wkr  = (const float*)d_in[14]; const float* bkr  = (const float*)d_in[15];
    const float* Wfc  = (const float*)d_in[16]; const float* bfc  = (const float*)d_in[17];
    float* out = (float*)d_out;

    float *ckv, *cq, *krl, *kc, *vc, *qc, *qr, *ao;
    cudaGetSymbolAddress((void**)&ckv, g_ckv);
    cudaGetSymbolAddress((void**)&cq,  g_cq);
    cudaGetSymbolAddress((void**)&krl, g_krl);
    cudaGetSymbolAddress((void**)&kc,  g_kc);
    cudaGetSymbolAddress((void**)&vc,  g_vc);
    cudaGetSymbolAddress((void**)&qc,  g_qc);
    cudaGetSymbolAddress((void**)&qr,  g_qr);
    cudaGetSymbolAddress((void**)&ao,  g_ao);

    const int ATT_SMEM = (2*64*97 + 64*65) * (int)sizeof(float);  // 66304 B
    cudaFuncSetAttribute(attn_kernel,
                         cudaFuncAttributeMaxDynamicSharedMemorySize, ATT_SMEM);

    // projections (gemm128: M,N multiples of 128)
    gemm128<<<dim3(DOWN_/128, MROWS/128), 256>>>(h,   Wdkv, bdkv, ckv, MROWS, DOWN_, D_);
    gemm128<<<dim3(DOWN_/128, MROWS/128), 256>>>(h,   Wdq,  bdq,  cq,  MROWS, DOWN_, D_);
    gemm_bias<<<dim3(1, MROWS/128), 256>>>(h, Wkr, bkr, krl, MROWS, RD_, D_);
    gemm128<<<dim3(UP_/128,  MROWS/128), 256>>>(ckv, Wuk, buk, kc, MROWS, UP_,    DOWN_);
    gemm128<<<dim3(UP_/128,  MROWS/128), 256>>>(ckv, Wuv, buv, vc, MROWS, UP_,    DOWN_);
    gemm128<<<dim3(UP_/128,  MROWS/128), 256>>>(cq,  Wuq, buq, qc, MROWS, UP_,    DOWN_);
    gemm128<<<dim3((RD_*H_)/128, MROWS/128), 256>>>(cq, Wqr, bqr, qr, MROWS, RD_*H_, DOWN_);

    // RoPE (negated angle)
    rope_kernel<<<MROWS, 256>>>(qr,  H_, RD_*H_);
    rope_kernel<<<MROWS, 32>>>(krl, 1,  RD_);

    // fused causal flash attention
    attn_kernel<<<dim3(S_/64, H_, BS_), 128, ATT_SMEM>>>(qc, qr, kc, krl, vc, ao);

    // output projection
    gemm128<<<dim3(D_/128, MROWS/128), 256>>>(ao, Wfc, bfc, out, MROWS, D_, UP_);
}

// round 11
// speedup vs baseline: 1.5717x; 1.1310x over previous
#include <cuda_runtime.h>
#include <math.h>
#include <stdint.h>

#define BS_   2
#define S_    2048
#define D_    2048
#define DOWN_ 512
#define UP_   1024
#define H_    16
#define RD_   32
#define MROWS (BS_*S_)

#define INVSCALE (1.0f/16.970562748477139f)

__device__ float g_ckv[MROWS*DOWN_];
__device__ float g_cq [MROWS*DOWN_];
__device__ float g_krl[MROWS*RD_];
__device__ float g_kc [MROWS*UP_];
__device__ float g_vc [MROWS*UP_];
__device__ float g_qc [MROWS*UP_];
__device__ float g_qr [MROWS*(RD_*H_)];
__device__ float g_ao [MROWS*UP_];

// ---------------- tf32 helpers ----------------
__device__ __forceinline__ uint32_t tf32_cvt(float x) {
    uint32_t u;
    asm("cvt.rna.tf32.f32 %0, %1;" : "=r"(u) : "f"(x));
    return u;
}
__device__ __forceinline__ void split_tf32(float x, uint32_t& hi, uint32_t& lo) {
    hi = tf32_cvt(x);
    lo = tf32_cvt(x - __uint_as_float(hi));
}
__device__ __forceinline__ void mma_tf32(float* d, const uint32_t* a,
                                         const uint32_t* b) {
    asm volatile(
        "mma.sync.aligned.m16n8k8.row.col.f32.tf32.tf32.f32 "
        "{%0,%1,%2,%3},{%4,%5,%6,%7},{%8,%9},{%0,%1,%2,%3};"
        : "+f"(d[0]), "+f"(d[1]), "+f"(d[2]), "+f"(d[3])
        : "r"(a[0]), "r"(a[1]), "r"(a[2]), "r"(a[3]), "r"(b[0]), "r"(b[1]));
}

// ---- tensor-core GEMM (3xTF32): C[M,N] = A[M,K] @ B[N,K]^T + bias ----
// 128x128 tile, BK=32, 256 threads (8 warps, 2x4), warp tile 64x32.
// Requires M%128==0, N%128==0, K%32==0.
#define SA_PITCH 36
__global__ void __launch_bounds__(256, 1) gemm_tf32(
    const float* __restrict__ A, const float* __restrict__ Bw,
    const float* __restrict__ bias, float* __restrict__ C,
    int M, int N, int K)
{
    extern __shared__ float sm[];
    float* As = sm;                       // [2][128][36]
    float* Bs = sm + 2*128*SA_PITCH;      // [2][128][36]

    const int tid  = threadIdx.x;
    const int lane = tid & 31, warp = tid >> 5;
    const int wm = warp >> 2, wn = warp & 3;        // 2 x 4
    const int lr = lane >> 2, lc = lane & 3;
    const int rowBase = blockIdx.y*128, colBase = blockIdx.x*128;
    const float* Ag = A  + (size_t)rowBase*K;
    const float* Bg = Bw + (size_t)colBase*K;

    float acc[4][4][4];
    #pragma unroll
    for (int i = 0; i < 4; i++)
        #pragma unroll
        for (int j = 0; j < 4; j++)
            #pragma unroll
            for (int c = 0; c < 4; c++) acc[i][j][c] = 0.f;

    // preload stage 0
    #pragma unroll
    for (int i = 0; i < 4; i++) {
        int q = tid + i*256;
        int row = q >> 3, kq = (q & 7)*4;
        float4 va = *(const float4*)(Ag + (size_t)row*K + kq);
        float* da = As + row*SA_PITCH + kq;
        da[0]=va.x; da[1]=va.y; da[2]=va.z; da[3]=va.w;
        float4 vb = *(const float4*)(Bg + (size_t)row*K + kq);
        float* db = Bs + row*SA_PITCH + kq;
        db[0]=vb.x; db[1]=vb.y; db[2]=vb.z; db[3]=vb.w;
    }
    __syncthreads();

    const int nK = K >> 5;
    for (int t = 0; t < nK; t++) {
        const int cur = t & 1;
        if (t + 1 < nK) {
            const int nxt = cur ^ 1;
            const int k0 = (t + 1) << 5;
            #pragma unroll
            for (int i = 0; i < 4; i++) {
                int q = tid + i*256;
                int row = q >> 3, kq = (q & 7)*4;
                float4 va = *(const float4*)(Ag + (size_t)row*K + k0 + kq);
                float* da = As + (nxt*128 + row)*SA_PITCH + kq;
                da[0]=va.x; da[1]=va.y; da[2]=va.z; da[3]=va.w;
                float4 vb = *(const float4*)(Bg + (size_t)row*K + k0 + kq);
                float* db = Bs + (nxt*128 + row)*SA_PITCH + kq;
                db[0]=vb.x; db[1]=vb.y; db[2]=vb.z; db[3]=vb.w;
            }
        }

        const float* Ac = As + cur*128*SA_PITCH;
        const float* Bc = Bs + cur*128*SA_PITCH;
        #pragma unroll
        for (int k8 = 0; k8 < 4; k8++) {
            const int ko = k8*8;
            uint32_t ahi[4][4], alo[4][4];
            #pragma unroll
            for (int mi = 0; mi < 4; mi++) {
                const float* base = Ac + (wm*64 + mi*16)*SA_PITCH + ko;
                float x0 = base[lr*SA_PITCH + lc];
                float x1 = base[(lr + 8)*SA_PITCH + lc];
                float x2 = base[lr*SA_PITCH + lc + 4];
                float x3 = base[(lr + 8)*SA_PITCH + lc + 4];
                split_tf32(x0, ahi[mi][0], alo[mi][0]);
                split_tf32(x1, ahi[mi][1], alo[mi][1]);
                split_tf32(x2, ahi[mi][2], alo[mi][2]);
                split_tf32(x3, ahi[mi][3], alo[mi][3]);
            }
            uint32_t bhi[4][2], blo[4][2];
            #pragma unroll
            for (int ni = 0; ni < 4; ni++) {
                const float* base = Bc + (wn*32 + ni*8)*SA_PITCH + ko;
                float y0 = base[lr*SA_PITCH + lc];
                float y1 = base[lr*SA_PITCH + lc + 4];
                split_tf32(y0, bhi[ni][0], blo[ni][0]);
                split_tf32(y1, bhi[ni][1], blo[ni][1]);
            }
            #pragma unroll
            for (int mi = 0; mi < 4; mi++)
                #pragma unroll
                for (int ni = 0; ni < 4; ni++) {
                    mma_tf32(acc[mi][ni], ahi[mi], bhi[ni]);
                    mma_tf32(acc[mi][ni], ahi[mi], blo[ni]);
                    mma_tf32(acc[mi][ni], alo[mi], bhi[ni]);
                }
        }
        __syncthreads();
    }

    // epilogue
    #pragma unroll
    for (int mi = 0; mi < 4; mi++) {
        #pragma unroll
        for (int ni = 0; ni < 4; ni++) {
            int r0 = rowBase + wm*64 + mi*16 + lr;
            int c0 = colBase + wn*32 + ni*8 + lc*2;
            float2 bv = *(const float2*)&bias[c0];
            float2 v0 = {acc[mi][ni][0] + bv.x, acc[mi][ni][1] + bv.y};
            float2 v1 = {acc[mi][ni][2] + bv.x, acc[mi][ni][3] + bv.y};
            *(float2*)&C[(size_t)r0*N + c0]       = v0;
            *(float2*)&C[(size_t)(r0 + 8)*N + c0] = v1;
        }
    }
}

// ---- small-N GEMM (for Wkr, N=32) ----
__global__ void __launch_bounds__(256) gemm_bias(
    const float* __restrict__ A, const float* __restrict__ Bw,
    const float* __restrict__ bias, float* __restrict__ C,
    int M, int N, int K)
{
    __shared__ float As[128][17];
    __shared__ float Bs[64][17];
    const int tid = threadIdx.x;
    const int ty = tid >> 3, tx = tid & 7;
    const int rowBase = blockIdx.y * 128, colBase = blockIdx.x * 64;
    float acc[4][8];
    #pragma unroll
    for (int i = 0; i < 4; i++)
        #pragma unroll
        for (int j = 0; j < 8; j++) acc[i][j] = 0.f;

    for (int k0 = 0; k0 < K; k0 += 16) {
        #pragma unroll
        for (int i = 0; i < 8; i++) {
            int lin = tid + i*256, r = lin >> 4, c = lin & 15;
            As[r][c] = A[(size_t)(rowBase + r)*K + k0 + c];
        }
        #pragma unroll
        for (int i = 0; i < 4; i++) {
            int lin = tid + i*256, r = lin >> 4, c = lin & 15;
            int gr = colBase + r;
            Bs[r][c] = (gr < N) ? Bw[(size_t)gr*K + k0 + c] : 0.f;
        }
        __syncthreads();
        #pragma unroll
        for (int kk = 0; kk < 16; kk++) {
            float a[4], b[8];
            #pragma unroll
            for (int i = 0; i < 4; i++) a[i] = As[ty*4 + i][kk];
            #pragma unroll
            for (int j = 0; j < 8; j++) b[j] = Bs[tx + 8*j][kk];
            #pragma unroll
            for (int i = 0; i < 4; i++)
                #pragma unroll
                for (int j = 0; j < 8; j++)
                    acc[i][j] = fmaf(a[i], b[j], acc[i][j]);
        }
        __syncthreads();
    }
    #pragma unroll
    for (int i = 0; i < 4; i++) {
        int r = rowBase + ty*4 + i;
        #pragma unroll
        for (int j = 0; j < 8; j++) {
            int cN = colBase + tx + 8*j;
            if (cN < N) C[(size_t)r*N + cN] = acc[i][j] + bias[cN];
        }
    }
}

// ---- RoPE in place, head_dim 32, NEGATED angle (matches reference) ----
__global__ void rope_kernel(float* __restrict__ x, int nheads, int rowStride)
{
    int row = blockIdx.x;
    int pos = row & (S_ - 1);
    int t = threadIdx.x;
    if (t >= nheads*16) return;
    int hh = t >> 4, j = t & 15;
    float* p = x + (size_t)row*rowStride + hh*32;
    double lf = -(double)j * (log(10000.0) / 16.0);
    float inv_freq = (float)exp(lf);
    float theta = (float)pos * inv_freq;
    float c, sn;
    sincosf(theta, &c, &sn);
    float x1 = p[j], x2 = p[j + 16];
    p[j]      = x1*c + x2*sn;
    p[j + 16] = x2*c - x1*sn;
}

// ---- Flash attention (causal), fp32 ----
__global__ void __launch_bounds__(128) attn_kernel(
    const float* __restrict__ qc, const float* __restrict__ qrr,
    const float* __restrict__ kc, const float* __restrict__ krr,
    const float* __restrict__ vc, float* __restrict__ out)
{
    extern __shared__ float smf[];
    float* Qs = smf;               // [64][97]
    float* Ks = smf + 64*97;       // [64][97], reused for P
    float* Vs = smf + 2*64*97;     // [64][65]

    const int tid = threadIdx.x;
    const int ty  = tid >> 3;
    const int tx  = tid & 7;
    const int qb = blockIdx.x, h = blockIdx.y, b = blockIdx.z;
    const int qs = qb * 64;
    const int rowOff = b * S_;

    for (int idx = tid; idx < 64*96; idx += 128) {
        int r = idx / 96, c = idx - r*96;
        int grow = rowOff + qs + r;
        Qs[r*97 + c] = (c < 64) ? qc[(size_t)grow*UP_ + h*64 + c]
                                : qrr[(size_t)grow*(RD_*H_) + h*32 + (c - 64)];
    }

    float m[4], l[4], o[4][8];
    #pragma unroll
    for (int i = 0; i < 4; i++) {
        m[i] = -1e30f; l[i] = 0.f;
        #pragma unroll
        for (int j = 0; j < 8; j++) o[i][j] = 0.f;
    }

    for (int kb = 0; kb <= qs; kb += 64) {
        __syncthreads();
        for (int idx = tid; idx < 64*96; idx += 128) {
            int r = idx / 96, c = idx - r*96;
            int grow = rowOff + kb + r;
            Ks[r*97 + c] = (c < 64) ? kc[(size_t)grow*UP_ + h*64 + c]
                                    : krr[(size_t)grow*RD_ + (c - 64)];
        }
        for (int idx = tid; idx < 64*64; idx += 128) {
            int r = idx >> 6, c = idx & 63;
            Vs[r*65 + c] = vc[(size_t)(rowOff + kb + r)*UP_ + h*64 + c];
        }
        __syncthreads();

        float s[4][8];
        #pragma unroll
        for (int i = 0; i < 4; i++)
            #pragma unroll
            for (int j = 0; j < 8; j++) s[i][j] = 0.f;

        #pragma unroll 4
        for (int kk = 0; kk < 96; kk++) {
            float a[4], bb[8];
            #pragma unroll
            for (int i = 0; i < 4; i++) a[i] = Qs[(ty*4 + i)*97 + kk];
            #pragma unroll
            for (int j = 0; j < 8; j++) bb[j] = Ks[(tx + 8*j)*97 + kk];
            #pragma unroll
            for (int i = 0; i < 4; i++)
                #pragma unroll
                for (int j = 0; j < 8; j++)
                    s[i][j] = fmaf(a[i], bb[j], s[i][j]);
        }

        const bool maskBlk = (kb == qs);
        #pragma unroll
        for (int i = 0; i < 4; i++)
            #pragma unroll
            for (int j = 0; j < 8; j++) {
                float v = s[i][j] * INVSCALE;
                if (maskBlk && (kb + tx + 8*j > qs + ty*4 + i)) v = -1e30f;
                s[i][j] = v;
            }

        #pragma unroll
        for (int i = 0; i < 4; i++) {
            float rm = s[i][0];
            #pragma unroll
            for (int j = 1; j < 8; j++) rm = fmaxf(rm, s[i][j]);
            rm = fmaxf(rm, __shfl_xor_sync(0xffffffffu, rm, 1));
            rm = fmaxf(rm, __shfl_xor_sync(0xffffffffu, rm, 2));
            rm = fmaxf(rm, __shfl_xor_sync(0xffffffffu, rm, 4));
            float mn = fmaxf(m[i], rm);
            float corr = __expf(m[i] - mn);
            l[i] *= corr;
            #pragma unroll
            for (int j = 0; j < 8; j++) o[i][j] *= corr;
            float rs = 0.f;
            #pragma unroll
            for (int j = 0; j < 8; j++) {
                float p = __expf(s[i][j] - mn);
                s[i][j] = p; rs += p;
            }
            rs += __shfl_xor_sync(0xffffffffu, rs, 1);
            rs += __shfl_xor_sync(0xffffffffu, rs, 2);
            rs += __shfl_xor_sync(0xffffffffu, rs, 4);
            l[i] += rs; m[i] = mn;
        }

        __syncthreads();
        #pragma unroll
        for (int i = 0; i < 4; i++)
            #pragma unroll
            for (int j = 0; j < 8; j++)
                Ks[(ty*4 + i)*97 + tx + 8*j] = s[i][j];
        __syncthreads();

        #pragma unroll 4
        for (int k = 0; k < 64; k++) {
            float p[4], vv[8];
            #pragma unroll
            for (int i = 0; i < 4; i++) p[i] = Ks[(ty*4 + i)*97 + k];
            #pragma unroll
            for (int j = 0; j < 8; j++) vv[j] = Vs[k*65 + tx + 8*j];
            #pragma unroll
            for (int i = 0; i < 4; i++)
                #pragma unroll
                for (int j = 0; j < 8; j++)
                    o[i][j] = fmaf(p[i], vv[j], o[i][j]);
        }
    }

    #pragma unroll
    for (int i = 0; i < 4; i++) {
        float inv = 1.f / l[i];
        int grow = rowOff + qs + ty*4 + i;
        #pragma unroll
        for (int j = 0; j < 8; j++)
            out[(size_t)grow*UP_ + h*64 + tx + 8*j] = o[i][j] * inv;
    }
}

extern "C" void kernel_launch(void* const* d_in, const int* in_sizes, int n_in,
                              void* d_out, int out_size)
{
    const float* h    = (const float*)d_in[0];
    const float* Wdkv = (const float*)d_in[2];  const float* bdkv = (const float*)d_in[3];
    const float* Wuk  = (const float*)d_in[4];  const float* buk  = (const float*)d_in[5];
    const float* Wuv  = (const float*)d_in[6];  const float* buv  = (const float*)d_in[7];
    const float* Wdq  = (const float*)d_in[8];  const float* bdq  = (const float*)d_in[9];
    const float* Wuq  = (const float*)d_in[10]; const float* buq  = (const float*)d_in[11];
    const float* Wqr  = (const float*)d_in[12]; const float* bqr  = (const float*)d_in[13];
    const float* Wkr  = (const float*)d_in[14]; const float* bkr  = (const float*)d_in[15];
    const float* Wfc  = (const float*)d_in[16]; const float* bfc  = (const float*)d_in[17];
    float* out = (float*)d_out;

    float *ckv, *cq, *krl, *kc, *vc, *qc, *qr, *ao;
    cudaGetSymbolAddress((void**)&ckv, g_ckv);
    cudaGetSymbolAddress((void**)&cq,  g_cq);
    cudaGetSymbolAddress((void**)&krl, g_krl);
    cudaGetSymbolAddress((void**)&kc,  g_kc);
    cudaGetSymbolAddress((void**)&vc,  g_vc);
    cudaGetSymbolAddress((void**)&qc,  g_qc);
    cudaGetSymbolAddress((void**)&qr,  g_qr);
    cudaGetSymbolAddress((void**)&ao,  g_ao);

    const int ATT_SMEM  = (2*64*97 + 64*65) * (int)sizeof(float);  // 66304 B
    const int GEMM_SMEM = 4*128*SA_PITCH*(int)sizeof(float);       // 73728 B
    cudaFuncSetAttribute(attn_kernel,
                         cudaFuncAttributeMaxDynamicSharedMemorySize, ATT_SMEM);
    cudaFuncSetAttribute(gemm_tf32,
                         cudaFuncAttributeMaxDynamicSharedMemorySize, GEMM_SMEM);

    // projections (tensor-core tf32x3)
    gemm_tf32<<<dim3(DOWN_/128, MROWS/128), 256, GEMM_SMEM>>>(h,   Wdkv, bdkv, ckv, MROWS, DOWN_, D_);
    gemm_tf32<<<dim3(DOWN_/128, MROWS/128), 256, GEMM_SMEM>>>(h,   Wdq,  bdq,  cq,  MROWS, DOWN_, D_);
    gemm_bias<<<dim3(1, MROWS/128), 256>>>(h, Wkr, bkr, krl, MROWS, RD_, D_);
    gemm_tf32<<<dim3(UP_/128,  MROWS/128), 256, GEMM_SMEM>>>(ckv, Wuk, buk, kc, MROWS, UP_,    DOWN_);
    gemm_tf32<<<dim3(UP_/128,  MROWS/128), 256, GEMM_SMEM>>>(ckv, Wuv, buv, vc, MROWS, UP_,    DOWN_);
    gemm_tf32<<<dim3(UP_/128,  MROWS/128), 256, GEMM_SMEM>>>(cq,  Wuq, buq, qc, MROWS, UP_,    DOWN_);
    gemm_tf32<<<dim3((RD_*H_)/128, MROWS/128), 256, GEMM_SMEM>>>(cq, Wqr, bqr, qr, MROWS, RD_*H_, DOWN_);

    // RoPE (negated angle)
    rope_kernel<<<MROWS, 256>>>(qr,  H_, RD_*H_);
    rope_kernel<<<MROWS, 32>>>(krl, 1,  RD_);

    // fused causal flash attention
    attn_kernel<<<dim3(S_/64, H_, BS_), 128, ATT_SMEM>>>(qc, qr, kc, krl, vc, ao);

    // output projection
    gemm_tf32<<<dim3(D_/128, MROWS/128), 256, GEMM_SMEM>>>(ao, Wfc, bfc, out, MROWS, D_, UP_);
}

// round 12
// speedup vs baseline: 1.8490x; 1.1764x over previous
#include <cuda_runtime.h>
#include <cuda_bf16.h>
#include <math.h>
#include <stdint.h>

#define BS_   2
#define S_    2048
#define D_    2048
#define DOWN_ 512
#define UP_   1024
#define H_    16
#define RD_   32
#define MROWS (BS_*S_)

#define INVSCALE (1.0f/16.970562748477139f)

__device__ float g_ckv[MROWS*DOWN_];
__device__ float g_cq [MROWS*DOWN_];
__device__ float g_krl[MROWS*RD_];
__device__ float g_kc [MROWS*UP_];
__device__ float g_vc [MROWS*UP_];
__device__ float g_qc [MROWS*UP_];
__device__ float g_qr [MROWS*(RD_*H_)];
__device__ float g_ao [MROWS*UP_];

// ---------------- bf16 helpers ----------------
__device__ __forceinline__ void mma_bf16(float* d, const uint32_t* a,
                                         const uint32_t* b) {
    asm volatile(
        "mma.sync.aligned.m16n8k16.row.col.f32.bf16.bf16.f32 "
        "{%0,%1,%2,%3},{%4,%5,%6,%7},{%8,%9},{%0,%1,%2,%3};"
        : "+f"(d[0]), "+f"(d[1]), "+f"(d[2]), "+f"(d[3])
        : "r"(a[0]), "r"(a[1]), "r"(a[2]), "r"(a[3]), "r"(b[0]), "r"(b[1]));
}
__device__ __forceinline__ uint32_t bf2_as_u32(__nv_bfloat162 v) {
    return *reinterpret_cast<uint32_t*>(&v);
}

// ---- tensor-core GEMM (3xBF16): C[M,N] = A[M,K] @ B[N,K]^T + bias ----
// 128x128 tile, BK=32, 256 threads (8 warps, 2x4), warp tile 64x32.
// smem: hi/lo bf16 planes, split once at load. Requires M%128==0, N%128==0, K%32==0.
#define PBK   20                 // u32 pitch per row (16 data + 4 pad)
#define PLANE (128*PBK)          // u32 per plane
__global__ void __launch_bounds__(256, 1) gemm_bf16x3(
    const float* __restrict__ A, const float* __restrict__ Bw,
    const float* __restrict__ bias, float* __restrict__ C,
    int M, int N, int K)
{
    extern __shared__ uint32_t smu[];
    // stage s: [Ahi | Alo | Bhi | Blo] each PLANE u32
    const int tid  = threadIdx.x;
    const int lane = tid & 31, warp = tid >> 5;
    const int wm = warp >> 2, wn = warp & 3;        // 2 x 4
    const int lr = lane >> 2, lc = lane & 3;
    const int rowBase = blockIdx.y*128, colBase = blockIdx.x*128;
    const float* Ag = A  + (size_t)rowBase*K;
    const float* Bg = Bw + (size_t)colBase*K;

    float acc[4][4][4];
    #pragma unroll
    for (int i = 0; i < 4; i++)
        #pragma unroll
        for (int j = 0; j < 4; j++)
            #pragma unroll
            for (int c = 0; c < 4; c++) acc[i][j][c] = 0.f;

    auto load_stage = [&](int st, int k0) {
        uint32_t* base = smu + st*4*PLANE;
        #pragma unroll
        for (int i = 0; i < 4; i++) {
            int q = tid + i*256;
            int row = q >> 3, kq = (q & 7)*4;
            int col = kq >> 1;
            uint32_t* dst = base + row*PBK + col;
            float4 va = *(const float4*)(Ag + (size_t)row*K + k0 + kq);
            __nv_bfloat162 h01 = __floats2bfloat162_rn(va.x, va.y);
            __nv_bfloat162 h23 = __floats2bfloat162_rn(va.z, va.w);
            float l0 = va.x - __low2float(h01), l1 = va.y - __high2float(h01);
            float l2 = va.z - __low2float(h23), l3 = va.w - __high2float(h23);
            dst[0] = bf2_as_u32(h01); dst[1] = bf2_as_u32(h23);
            dst[PLANE+0] = bf2_as_u32(__floats2bfloat162_rn(l0, l1));
            dst[PLANE+1] = bf2_as_u32(__floats2bfloat162_rn(l2, l3));
            float4 vb = *(const float4*)(Bg + (size_t)row*K + k0 + kq);
            __nv_bfloat162 g01 = __floats2bfloat162_rn(vb.x, vb.y);
            __nv_bfloat162 g23 = __floats2bfloat162_rn(vb.z, vb.w);
            float m0 = vb.x - __low2float(g01), m1 = vb.y - __high2float(g01);
            float m2 = vb.z - __low2float(g23), m3 = vb.w - __high2float(g23);
            dst[2*PLANE+0] = bf2_as_u32(g01); dst[2*PLANE+1] = bf2_as_u32(g23);
            dst[3*PLANE+0] = bf2_as_u32(__floats2bfloat162_rn(m0, m1));
            dst[3*PLANE+1] = bf2_as_u32(__floats2bfloat162_rn(m2, m3));
        }
    };

    load_stage(0, 0);
    __syncthreads();

    const int nK = K >> 5;
    for (int t = 0; t < nK; t++) {
        const int cur = t & 1;
        if (t + 1 < nK) load_stage(cur ^ 1, (t + 1) << 5);

        const uint32_t* Ah = smu + cur*4*PLANE;
        #pragma unroll
        for (int s = 0; s < 2; s++) {            // two k16 steps
            const int colb = s*8;
            uint32_t ah[4][4], al[4][4];
            #pragma unroll
            for (int mi = 0; mi < 4; mi++) {
                const uint32_t* pa = Ah + (wm*64 + mi*16 + lr)*PBK + colb + lc;
                ah[mi][0] = pa[0];         ah[mi][2] = pa[4];
                ah[mi][1] = pa[8*PBK];     ah[mi][3] = pa[8*PBK + 4];
                const uint32_t* qa = pa + PLANE;
                al[mi][0] = qa[0];         al[mi][2] = qa[4];
                al[mi][1] = qa[8*PBK];     al[mi][3] = qa[8*PBK + 4];
            }
            uint32_t bh[4][2], bl[4][2];
            #pragma unroll
            for (int ni = 0; ni < 4; ni++) {
                const uint32_t* pb = Ah + 2*PLANE + (wn*32 + ni*8 + lr)*PBK + colb + lc;
                bh[ni][0] = pb[0];  bh[ni][1] = pb[4];
                bl[ni][0] = pb[PLANE]; bl[ni][1] = pb[PLANE + 4];
            }
            #pragma unroll
            for (int mi = 0; mi < 4; mi++)
                #pragma unroll
                for (int ni = 0; ni < 4; ni++) {
                    mma_bf16(acc[mi][ni], ah[mi], bh[ni]);
                    mma_bf16(acc[mi][ni], ah[mi], bl[ni]);
                    mma_bf16(acc[mi][ni], al[mi], bh[ni]);
                }
        }
        __syncthreads();
    }

    #pragma unroll
    for (int mi = 0; mi < 4; mi++) {
        #pragma unroll
        for (int ni = 0; ni < 4; ni++) {
            int r0 = rowBase + wm*64 + mi*16 + lr;
            int c0 = colBase + wn*32 + ni*8 + lc*2;
            float2 bv = *(const float2*)&bias[c0];
            float2 v0 = {acc[mi][ni][0] + bv.x, acc[mi][ni][1] + bv.y};
            float2 v1 = {acc[mi][ni][2] + bv.x, acc[mi][ni][3] + bv.y};
            *(float2*)&C[(size_t)r0*N + c0]       = v0;
            *(float2*)&C[(size_t)(r0 + 8)*N + c0] = v1;
        }
    }
}

// ---- small-N GEMM (for Wkr, N=32) ----
__global__ void __launch_bounds__(256) gemm_bias(
    const float* __restrict__ A, const float* __restrict__ Bw,
    const float* __restrict__ bias, float* __restrict__ C,
    int M, int N, int K)
{
    __shared__ float As[128][17];
    __shared__ float Bs[64][17];
    const int tid = threadIdx.x;
    const int ty = tid >> 3, tx = tid & 7;
    const int rowBase = blockIdx.y * 128, colBase = blockIdx.x * 64;
    float acc[4][8];
    #pragma unroll
    for (int i = 0; i < 4; i++)
        #pragma unroll
        for (int j = 0; j < 8; j++) acc[i][j] = 0.f;

    for (int k0 = 0; k0 < K; k0 += 16) {
        #pragma unroll
        for (int i = 0; i < 8; i++) {
            int lin = tid + i*256, r = lin >> 4, c = lin & 15;
            As[r][c] = A[(size_t)(rowBase + r)*K + k0 + c];
        }
        #pragma unroll
        for (int i = 0; i < 4; i++) {
            int lin = tid + i*256, r = lin >> 4, c = lin & 15;
            int gr = colBase + r;
            Bs[r][c] = (gr < N) ? Bw[(size_t)gr*K + k0 + c] : 0.f;
        }
        __syncthreads();
        #pragma unroll
        for (int kk = 0; kk < 16; kk++) {
            float a[4], b[8];
            #pragma unroll
            for (int i = 0; i < 4; i++) a[i] = As[ty*4 + i][kk];
            #pragma unroll
            for (int j = 0; j < 8; j++) b[j] = Bs[tx + 8*j][kk];
            #pragma unroll
            for (int i = 0; i < 4; i++)
                #pragma unroll
                for (int j = 0; j < 8; j++)
                    acc[i][j] = fmaf(a[i], b[j], acc[i][j]);
        }
        __syncthreads();
    }
    #pragma unroll
    for (int i = 0; i < 4; i++) {
        int r = rowBase + ty*4 + i;
        #pragma unroll
        for (int j = 0; j < 8; j++) {
            int cN = colBase + tx + 8*j;
            if (cN < N) C[(size_t)r*N + cN] = acc[i][j] + bias[cN];
        }
    }
}

// ---- RoPE in place, head_dim 32, NEGATED angle (matches reference) ----
__global__ void rope_kernel(float* __restrict__ x, int nheads, int rowStride)
{
    int row = blockIdx.x;
    int pos = row & (S_ - 1);
    int t = threadIdx.x;
    if (t >= nheads*16) return;
    int hh = t >> 4, j = t & 15;
    float* p = x + (size_t)row*rowStride + hh*32;
    double lf = -(double)j * (log(10000.0) / 16.0);
    float inv_freq = (float)exp(lf);
    float theta = (float)pos * inv_freq;
    float c, sn;
    sincosf(theta, &c, &sn);
    float x1 = p[j], x2 = p[j + 16];
    p[j]      = x1*c + x2*sn;
    p[j + 16] = x2*c - x1*sn;
}

// ---- Flash attention (causal), fp32 ----
__global__ void __launch_bounds__(128) attn_kernel(
    const float* __restrict__ qc, const float* __restrict__ qrr,
    const float* __restrict__ kc, const float* __restrict__ krr,
    const float* __restrict__ vc, float* __restrict__ out)
{
    extern __shared__ float smf[];
    float* Qs = smf;               // [64][97]
    float* Ks = smf + 64*97;       // [64][97], reused for P
    float* Vs = smf + 2*64*97;     // [64][65]

    const int tid = threadIdx.x;
    const int ty  = tid >> 3;
    const int tx  = tid & 7;
    const int qb = blockIdx.x, h = blockIdx.y, b = blockIdx.z;
    const int qs = qb * 64;
    const int rowOff = b * S_;

    for (int idx = tid; idx < 64*96; idx += 128) {
        int r = idx / 96, c = idx - r*96;
        int grow = rowOff + qs + r;
        Qs[r*97 + c] = (c < 64) ? qc[(size_t)grow*UP_ + h*64 + c]
                                : qrr[(size_t)grow*(RD_*H_) + h*32 + (c - 64)];
    }

    float m[4], l[4], o[4][8];
    #pragma unroll
    for (int i = 0; i < 4; i++) {
        m[i] = -1e30f; l[i] = 0.f;
        #pragma unroll
        for (int j = 0; j < 8; j++) o[i][j] = 0.f;
    }

    for (int kb = 0; kb <= qs; kb += 64) {
        __syncthreads();
        for (int idx = tid; idx < 64*96; idx += 128) {
            int r = idx / 96, c = idx - r*96;
            int grow = rowOff + kb + r;
            Ks[r*97 + c] = (c < 64) ? kc[(size_t)grow*UP_ + h*64 + c]
                                    : krr[(size_t)grow*RD_ + (c - 64)];
        }
        for (int idx = tid; idx < 64*64; idx += 128) {
            int r = idx >> 6, c = idx & 63;
            Vs[r*65 + c] = vc[(size_t)(rowOff + kb + r)*UP_ + h*64 + c];
        }
        __syncthreads();

        float s[4][8];
        #pragma unroll
        for (int i = 0; i < 4; i++)
            #pragma unroll
            for (int j = 0; j < 8; j++) s[i][j] = 0.f;

        #pragma unroll 4
        for (int kk = 0; kk < 96; kk++) {
            float a[4], bb[8];
            #pragma unroll
            for (int i = 0; i < 4; i++) a[i] = Qs[(ty*4 + i)*97 + kk];
            #pragma unroll
            for (int j = 0; j < 8; j++) bb[j] = Ks[(tx + 8*j)*97 + kk];
            #pragma unroll
            for (int i = 0; i < 4; i++)
                #pragma unroll
                for (int j = 0; j < 8; j++)
                    s[i][j] = fmaf(a[i], bb[j], s[i][j]);
        }

        const bool maskBlk = (kb == qs);
        #pragma unroll
        for (int i = 0; i < 4; i++)
            #pragma unroll
            for (int j = 0; j < 8; j++) {
                float v = s[i][j] * INVSCALE;
                if (maskBlk && (kb + tx + 8*j > qs + ty*4 + i)) v = -1e30f;
                s[i][j] = v;
            }

        #pragma unroll
        for (int i = 0; i < 4; i++) {
            float rm = s[i][0];
            #pragma unroll
            for (int j = 1; j < 8; j++) rm = fmaxf(rm, s[i][j]);
            rm = fmaxf(rm, __shfl_xor_sync(0xffffffffu, rm, 1));
            rm = fmaxf(rm, __shfl_xor_sync(0xffffffffu, rm, 2));
            rm = fmaxf(rm, __shfl_xor_sync(0xffffffffu, rm, 4));
            float mn = fmaxf(m[i], rm);
            float corr = __expf(m[i] - mn);
            l[i] *= corr;
            #pragma unroll
            for (int j = 0; j < 8; j++) o[i][j] *= corr;
            float rs = 0.f;
            #pragma unroll
            for (int j = 0; j < 8; j++) {
                float p = __expf(s[i][j] - mn);
                s[i][j] = p; rs += p;
            }
            rs += __shfl_xor_sync(0xffffffffu, rs, 1);
            rs += __shfl_xor_sync(0xffffffffu, rs, 2);
            rs += __shfl_xor_sync(0xffffffffu, rs, 4);
            l[i] += rs; m[i] = mn;
        }

        __syncthreads();
        #pragma unroll
        for (int i = 0; i < 4; i++)
            #pragma unroll
            for (int j = 0; j < 8; j++)
                Ks[(ty*4 + i)*97 + tx + 8*j] = s[i][j];
        __syncthreads();

        #pragma unroll 4
        for (int k = 0; k < 64; k++) {
            float p[4], vv[8];
            #pragma unroll
            for (int i = 0; i < 4; i++) p[i] = Ks[(ty*4 + i)*97 + k];
            #pragma unroll
            for (int j = 0; j < 8; j++) vv[j] = Vs[k*65 + tx + 8*j];
            #pragma unroll
            for (int i = 0; i < 4; i++)
                #pragma unroll
                for (int j = 0; j < 8; j++)
                    o[i][j] = fmaf(p[i], vv[j], o[i][j]);
        }
    }

    #pragma unroll
    for (int i = 0; i < 4; i++) {
        float inv = 1.f / l[i];
        int grow = rowOff + qs + ty*4 + i;
        #pragma unroll
        for (int j = 0; j < 8; j++)
            out[(size_t)grow*UP_ + h*64 + tx + 8*j] = o[i][j] * inv;
    }
}

extern "C" void kernel_launch(void* const* d_in, const int* in_sizes, int n_in,
                              void* d_out, int out_size)
{
    const float* h    = (const float*)d_in[0];
    const float* Wdkv = (const float*)d_in[2];  const float* bdkv = (const float*)d_in[3];
    const float* Wuk  = (const float*)d_in[4];  const float* buk  = (const float*)d_in[5];
    const float* Wuv  = (const float*)d_in[6];  const float* buv  = (const float*)d_in[7];
    const float* Wdq  = (const float*)d_in[8];  const float* bdq  = (const float*)d_in[9];
    const float* Wuq  = (const float*)d_in[10]; const float* buq  = (const float*)d_in[11];
    const float* Wqr  = (const float*)d_in[12]; const float* bqr  = (const float*)d_in[13];
    const float* Wkr  = (const float*)d_in[14]; const float* bkr  = (const float*)d_in[15];
    const float* Wfc  = (const float*)d_in[16]; const float* bfc  = (const float*)d_in[17];
    float* out = (float*)d_out;

    float *ckv, *cq, *krl, *kc, *vc, *qc, *qr, *ao;
    cudaGetSymbolAddress((void**)&ckv, g_ckv);
    cudaGetSymbolAddress((void**)&cq,  g_cq);
    cudaGetSymbolAddress((void**)&krl, g_krl);
    cudaGetSymbolAddress((void**)&kc,  g_kc);
    cudaGetSymbolAddress((void**)&vc,  g_vc);
    cudaGetSymbolAddress((void**)&qc,  g_qc);
    cudaGetSymbolAddress((void**)&qr,  g_qr);
    cudaGetSymbolAddress((void**)&ao,  g_ao);

    const int ATT_SMEM  = (2*64*97 + 64*65) * (int)sizeof(float);   // 66304 B
    const int GEMM_SMEM = 2*4*PLANE*(int)sizeof(uint32_t);          // 81920 B
    cudaFuncSetAttribute(attn_kernel,
                         cudaFuncAttributeMaxDynamicSharedMemorySize, ATT_SMEM);
    cudaFuncSetAttribute(gemm_bf16x3,
                         cudaFuncAttributeMaxDynamicSharedMemorySize, GEMM_SMEM);

    // projections (tensor-core 3xBF16)
    gemm_bf16x3<<<dim3(DOWN_/128, MROWS/128), 256, GEMM_SMEM>>>(h,   Wdkv, bdkv, ckv, MROWS, DOWN_, D_);
    gemm_bf16x3<<<dim3(DOWN_/128, MROWS/128), 256, GEMM_SMEM>>>(h,   Wdq,  bdq,  cq,  MROWS, DOWN_, D_);
    gemm_bias<<<dim3(1, MROWS/128), 256>>>(h, Wkr, bkr, krl, MROWS, RD_, D_);
    gemm_bf16x3<<<dim3(UP_/128,  MROWS/128), 256, GEMM_SMEM>>>(ckv, Wuk, buk, kc, MROWS, UP_,    DOWN_);
    gemm_bf16x3<<<dim3(UP_/128,  MROWS/128), 256, GEMM_SMEM>>>(ckv, Wuv, buv, vc, MROWS, UP_,    DOWN_);
    gemm_bf16x3<<<dim3(UP_/128,  MROWS/128), 256, GEMM_SMEM>>>(cq,  Wuq, buq, qc, MROWS, UP_,    DOWN_);
    gemm_bf16x3<<<dim3((RD_*H_)/128, MROWS/128), 256, GEMM_SMEM>>>(cq, Wqr, bqr, qr, MROWS, RD_*H_, DOWN_);

    // RoPE (negated angle)
    rope_kernel<<<MROWS, 256>>>(qr,  H_, RD_*H_);
    rope_kernel<<<MROWS, 32>>>(krl, 1,  RD_);

    // fused causal flash attention (fp32)
    attn_kernel<<<dim3(S_/64, H_, BS_), 128, ATT_SMEM>>>(qc, qr, kc, krl, vc, ao);

    // output projection
    gemm_bf16x3<<<dim3(D_/128, MROWS/128), 256, GEMM_SMEM>>>(ao, Wfc, bfc, out, MROWS, D_, UP_);
}

// round 13
// speedup vs baseline: 2.5501x; 1.3792x over previous
#include <cuda_runtime.h>
#include <cuda_bf16.h>
#include <math.h>
#include <stdint.h>

#define BS_   2
#define S_    2048
#define D_    2048
#define DOWN_ 512
#define UP_   1024
#define H_    16
#define RD_   32
#define MROWS (BS_*S_)

#define INVSCALE (1.0f/16.970562748477139f)

__device__ float g_ckv[MROWS*DOWN_];
__device__ float g_cq [MROWS*DOWN_];
__device__ float g_krl[MROWS*RD_];
__device__ float g_kc [MROWS*UP_];
__device__ float g_vc [MROWS*UP_];
__device__ float g_qc [MROWS*UP_];
__device__ float g_qr [MROWS*(RD_*H_)];
__device__ float g_ao [MROWS*UP_];

// ---------------- bf16 helpers ----------------
__device__ __forceinline__ void mma_bf16(float* d, const uint32_t* a,
                                         const uint32_t* b) {
    asm volatile(
        "mma.sync.aligned.m16n8k16.row.col.f32.bf16.bf16.f32 "
        "{%0,%1,%2,%3},{%4,%5,%6,%7},{%8,%9},{%0,%1,%2,%3};"
        : "+f"(d[0]), "+f"(d[1]), "+f"(d[2]), "+f"(d[3])
        : "r"(a[0]), "r"(a[1]), "r"(a[2]), "r"(a[3]), "r"(b[0]), "r"(b[1]));
}
__device__ __forceinline__ uint32_t bf2_as_u32(__nv_bfloat162 v) {
    return *reinterpret_cast<uint32_t*>(&v);
}

// fast exp on the FMA pipe (exp2 range reduction + degree-5 poly, ~2e-6 rel)
__device__ __forceinline__ float fexp(float x) {
    x = fmaxf(x, -87.0f);
    float t = x * 1.4426950408889634f;
    float n = rintf(t);
    float f = t - n;
    float p = 0.0013333558f;
    p = fmaf(p, f, 0.009618129f);
    p = fmaf(p, f, 0.0555041087f);
    p = fmaf(p, f, 0.2402265069f);
    p = fmaf(p, f, 0.6931471806f);
    p = fmaf(p, f, 1.0f);
    return p * __int_as_float(((int)n + 127) << 23);
}

// ---- tensor-core GEMM (3xBF16): C[M,N] = A[M,K] @ B[N,K]^T + bias ----
#define PBK   20
#define PLANE (128*PBK)
__global__ void __launch_bounds__(256, 1) gemm_bf16x3(
    const float* __restrict__ A, const float* __restrict__ Bw,
    const float* __restrict__ bias, float* __restrict__ C,
    int M, int N, int K)
{
    extern __shared__ uint32_t smu[];
    const int tid  = threadIdx.x;
    const int lane = tid & 31, warp = tid >> 5;
    const int wm = warp >> 2, wn = warp & 3;
    const int lr = lane >> 2, lc = lane & 3;
    const int rowBase = blockIdx.y*128, colBase = blockIdx.x*128;
    const float* Ag = A  + (size_t)rowBase*K;
    const float* Bg = Bw + (size_t)colBase*K;

    float acc[4][4][4];
    #pragma unroll
    for (int i = 0; i < 4; i++)
        #pragma unroll
        for (int j = 0; j < 4; j++)
            #pragma unroll
            for (int c = 0; c < 4; c++) acc[i][j][c] = 0.f;

    auto load_stage = [&](int st, int k0) {
        uint32_t* base = smu + st*4*PLANE;
        #pragma unroll
        for (int i = 0; i < 4; i++) {
            int q = tid + i*256;
            int row = q >> 3, kq = (q & 7)*4;
            int col = kq >> 1;
            uint32_t* dst = base + row*PBK + col;
            float4 va = *(const float4*)(Ag + (size_t)row*K + k0 + kq);
            __nv_bfloat162 h01 = __floats2bfloat162_rn(va.x, va.y);
            __nv_bfloat162 h23 = __floats2bfloat162_rn(va.z, va.w);
            float l0 = va.x - __low2float(h01), l1 = va.y - __high2float(h01);
            float l2 = va.z - __low2float(h23), l3 = va.w - __high2float(h23);
            dst[0] = bf2_as_u32(h01); dst[1] = bf2_as_u32(h23);
            dst[PLANE+0] = bf2_as_u32(__floats2bfloat162_rn(l0, l1));
            dst[PLANE+1] = bf2_as_u32(__floats2bfloat162_rn(l2, l3));
            float4 vb = *(const float4*)(Bg + (size_t)row*K + k0 + kq);
            __nv_bfloat162 g01 = __floats2bfloat162_rn(vb.x, vb.y);
            __nv_bfloat162 g23 = __floats2bfloat162_rn(vb.z, vb.w);
            float m0 = vb.x - __low2float(g01), m1 = vb.y - __high2float(g01);
            float m2 = vb.z - __low2float(g23), m3 = vb.w - __high2float(g23);
            dst[2*PLANE+0] = bf2_as_u32(g01); dst[2*PLANE+1] = bf2_as_u32(g23);
            dst[3*PLANE+0] = bf2_as_u32(__floats2bfloat162_rn(m0, m1));
            dst[3*PLANE+1] = bf2_as_u32(__floats2bfloat162_rn(m2, m3));
        }
    };

    load_stage(0, 0);
    __syncthreads();

    const int nK = K >> 5;
    for (int t = 0; t < nK; t++) {
        const int cur = t & 1;
        if (t + 1 < nK) load_stage(cur ^ 1, (t + 1) << 5);

        const uint32_t* Ah = smu + cur*4*PLANE;
        #pragma unroll
        for (int s = 0; s < 2; s++) {
            const int colb = s*8;
            uint32_t ah[4][4], al[4][4];
            #pragma unroll
            for (int mi = 0; mi < 4; mi++) {
                const uint32_t* pa = Ah + (wm*64 + mi*16 + lr)*PBK + colb + lc;
                ah[mi][0] = pa[0];         ah[mi][2] = pa[4];
                ah[mi][1] = pa[8*PBK];     ah[mi][3] = pa[8*PBK + 4];
                const uint32_t* qa = pa + PLANE;
                al[mi][0] = qa[0];         al[mi][2] = qa[4];
                al[mi][1] = qa[8*PBK];     al[mi][3] = qa[8*PBK + 4];
            }
            uint32_t bh[4][2], bl[4][2];
            #pragma unroll
            for (int ni = 0; ni < 4; ni++) {
                const uint32_t* pb = Ah + 2*PLANE + (wn*32 + ni*8 + lr)*PBK + colb + lc;
                bh[ni][0] = pb[0];  bh[ni][1] = pb[4];
                bl[ni][0] = pb[PLANE]; bl[ni][1] = pb[PLANE + 4];
            }
            #pragma unroll
            for (int mi = 0; mi < 4; mi++)
                #pragma unroll
                for (int ni = 0; ni < 4; ni++) {
                    mma_bf16(acc[mi][ni], ah[mi], bh[ni]);
                    mma_bf16(acc[mi][ni], ah[mi], bl[ni]);
                    mma_bf16(acc[mi][ni], al[mi], bh[ni]);
                }
        }
        __syncthreads();
    }

    #pragma unroll
    for (int mi = 0; mi < 4; mi++) {
        #pragma unroll
        for (int ni = 0; ni < 4; ni++) {
            int r0 = rowBase + wm*64 + mi*16 + lr;
            int c0 = colBase + wn*32 + ni*8 + lc*2;
            float2 bv = *(const float2*)&bias[c0];
            float2 v0 = {acc[mi][ni][0] + bv.x, acc[mi][ni][1] + bv.y};
            float2 v1 = {acc[mi][ni][2] + bv.x, acc[mi][ni][3] + bv.y};
            *(float2*)&C[(size_t)r0*N + c0]       = v0;
            *(float2*)&C[(size_t)(r0 + 8)*N + c0] = v1;
        }
    }
}

// ---- small-N GEMM (for Wkr, N=32) ----
__global__ void __launch_bounds__(256) gemm_bias(
    const float* __restrict__ A, const float* __restrict__ Bw,
    const float* __restrict__ bias, float* __restrict__ C,
    int M, int N, int K)
{
    __shared__ float As[128][17];
    __shared__ float Bs[64][17];
    const int tid = threadIdx.x;
    const int ty = tid >> 3, tx = tid & 7;
    const int rowBase = blockIdx.y * 128, colBase = blockIdx.x * 64;
    float acc[4][8];
    #pragma unroll
    for (int i = 0; i < 4; i++)
        #pragma unroll
        for (int j = 0; j < 8; j++) acc[i][j] = 0.f;

    for (int k0 = 0; k0 < K; k0 += 16) {
        #pragma unroll
        for (int i = 0; i < 8; i++) {
            int lin = tid + i*256, r = lin >> 4, c = lin & 15;
            As[r][c] = A[(size_t)(rowBase + r)*K + k0 + c];
        }
        #pragma unroll
        for (int i = 0; i < 4; i++) {
            int lin = tid + i*256, r = lin >> 4, c = lin & 15;
            int gr = colBase + r;
            Bs[r][c] = (gr < N) ? Bw[(size_t)gr*K + k0 + c] : 0.f;
        }
        __syncthreads();
        #pragma unroll
        for (int kk = 0; kk < 16; kk++) {
            float a[4], b[8];
            #pragma unroll
            for (int i = 0; i < 4; i++) a[i] = As[ty*4 + i][kk];
            #pragma unroll
            for (int j = 0; j < 8; j++) b[j] = Bs[tx + 8*j][kk];
            #pragma unroll
            for (int i = 0; i < 4; i++)
                #pragma unroll
                for (int j = 0; j < 8; j++)
                    acc[i][j] = fmaf(a[i], b[j], acc[i][j]);
        }
        __syncthreads();
    }
    #pragma unroll
    for (int i = 0; i < 4; i++) {
        int r = rowBase + ty*4 + i;
        #pragma unroll
        for (int j = 0; j < 8; j++) {
            int cN = colBase + tx + 8*j;
            if (cN < N) C[(size_t)r*N + cN] = acc[i][j] + bias[cN];
        }
    }
}

// ---- RoPE in place, head_dim 32, NEGATED angle (matches reference) ----
__global__ void rope_kernel(float* __restrict__ x, int nheads, int rowStride)
{
    int row = blockIdx.x;
    int pos = row & (S_ - 1);
    int t = threadIdx.x;
    if (t >= nheads*16) return;
    int hh = t >> 4, j = t & 15;
    float* p = x + (size_t)row*rowStride + hh*32;
    double lf = -(double)j * (log(10000.0) / 16.0);
    float inv_freq = (float)exp(lf);
    float theta = (float)pos * inv_freq;
    float c, sn;
    sincosf(theta, &c, &sn);
    float x1 = p[j], x2 = p[j + 16];
    p[j]      = x1*c + x2*sn;
    p[j + 16] = x2*c - x1*sn;
}

// ---- Flash attention (causal) on mma.sync bf16x3 ----
// CTA: 64 q-rows of one (b,h), 4 warps (warp = 16 rows). DQK=96, DV=64.
#define AP 52   // Q/K row pitch (u32, bf16x2-packed), 52 % 32 = 20 -> conflict-free
#define VP 36   // Vt row pitch (u32), 36 % 32 = 4 -> conflict-free
__global__ void __launch_bounds__(128) attn_mma(
    const float* __restrict__ qc, const float* __restrict__ qrr,
    const float* __restrict__ kc, const float* __restrict__ krr,
    const float* __restrict__ vc, float* __restrict__ out)
{
    extern __shared__ uint32_t su[];
    uint32_t* Qhi = su;                 // [64][AP]
    uint32_t* Qlo = Qhi + 64*AP;
    uint32_t* Khi = Qlo + 64*AP;
    uint32_t* Klo = Khi + 64*AP;
    uint32_t* Vhi = Klo + 64*AP;        // [64 dims][VP keypairs]
    uint32_t* Vlo = Vhi + 64*VP;
    uint16_t* VhiH = (uint16_t*)Vhi;
    uint16_t* VloH = (uint16_t*)Vlo;

    const int tid = threadIdx.x;
    const int lane = tid & 31, warp = tid >> 5;
    const int lr = lane >> 2, lc = lane & 3;
    const int qb = blockIdx.x, h = blockIdx.y, b = blockIdx.z;
    const int qs = qb*64;
    const int rowOff = b*S_;

    // load Q tile (rows qs..qs+63, 96 dims) split hi/lo
    for (int t = tid; t < 64*24; t += 128) {
        int r = t / 24, w = t - (t/24)*24;           // 4 dims per w
        int grow = rowOff + qs + r;
        float4 v = (w < 16)
            ? *(const float4*)(qc  + (size_t)grow*UP_      + h*64 + 4*w)
            : *(const float4*)(qrr + (size_t)grow*(RD_*H_) + h*32 + 4*(w-16));
        __nv_bfloat162 h01 = __floats2bfloat162_rn(v.x, v.y);
        __nv_bfloat162 h23 = __floats2bfloat162_rn(v.z, v.w);
        float e0 = v.x - __low2float(h01), e1 = v.y - __high2float(h01);
        float e2 = v.z - __low2float(h23), e3 = v.w - __high2float(h23);
        Qhi[r*AP + 2*w]   = bf2_as_u32(h01);
        Qhi[r*AP + 2*w+1] = bf2_as_u32(h23);
        Qlo[r*AP + 2*w]   = bf2_as_u32(__floats2bfloat162_rn(e0, e1));
        Qlo[r*AP + 2*w+1] = bf2_as_u32(__floats2bfloat162_rn(e2, e3));
    }

    float m0 = -1e30f, m1 = -1e30f, l0s = 0.f, l1s = 0.f;
    float o[8][4];
    #pragma unroll
    for (int j = 0; j < 8; j++)
        #pragma unroll
        for (int c = 0; c < 4; c++) o[j][c] = 0.f;

    for (int kb = 0; kb <= qs; kb += 64) {
        __syncthreads();
        // K tile split hi/lo
        for (int t = tid; t < 64*24; t += 128) {
            int r = t / 24, w = t - (t/24)*24;
            int grow = rowOff + kb + r;
            float4 v = (w < 16)
                ? *(const float4*)(kc  + (size_t)grow*UP_ + h*64 + 4*w)
                : *(const float4*)(krr + (size_t)grow*RD_ + 4*(w-16));
            __nv_bfloat162 h01 = __floats2bfloat162_rn(v.x, v.y);
            __nv_bfloat162 h23 = __floats2bfloat162_rn(v.z, v.w);
            float e0 = v.x - __low2float(h01), e1 = v.y - __high2float(h01);
            float e2 = v.z - __low2float(h23), e3 = v.w - __high2float(h23);
            Khi[r*AP + 2*w]   = bf2_as_u32(h01);
            Khi[r*AP + 2*w+1] = bf2_as_u32(h23);
            Klo[r*AP + 2*w]   = bf2_as_u32(__floats2bfloat162_rn(e0, e1));
            Klo[r*AP + 2*w+1] = bf2_as_u32(__floats2bfloat162_rn(e2, e3));
        }
        // V tile transposed [dim][key], split hi/lo
        for (int t = tid; t < 64*16; t += 128) {
            int r = t / 16, dq = t - (t/16)*16;
            int grow = rowOff + kb + r;
            float4 v = *(const float4*)(vc + (size_t)grow*UP_ + h*64 + 4*dq);
            float vv[4] = {v.x, v.y, v.z, v.w};
            #pragma unroll
            for (int e = 0; e < 4; e++) {
                int d = 4*dq + e;
                __nv_bfloat16 hb = __float2bfloat16_rn(vv[e]);
                float rem = vv[e] - __bfloat162float(hb);
                __nv_bfloat16 lb = __float2bfloat16_rn(rem);
                VhiH[d*(2*VP) + r] = *(uint16_t*)&hb;
                VloH[d*(2*VP) + r] = *(uint16_t*)&lb;
            }
        }
        __syncthreads();

        // S = Q K^T (3xBF16)
        float s[8][4];
        #pragma unroll
        for (int j = 0; j < 8; j++)
            #pragma unroll
            for (int c = 0; c < 4; c++) s[j][c] = 0.f;

        const uint32_t* qh = Qhi + (warp*16 + lr)*AP + lc;
        const uint32_t* ql = Qlo + (warp*16 + lr)*AP + lc;
        #pragma unroll
        for (int t = 0; t < 6; t++) {
            uint32_t ah[4], al[4];
            const uint32_t* pq = qh + t*8;
            ah[0]=pq[0]; ah[1]=pq[8*AP]; ah[2]=pq[4]; ah[3]=pq[8*AP+4];
            const uint32_t* pl = ql + t*8;
            al[0]=pl[0]; al[1]=pl[8*AP]; al[2]=pl[4]; al[3]=pl[8*AP+4];
            #pragma unroll
            for (int j = 0; j < 8; j++) {
                const uint32_t* pk = Khi + (8*j + lr)*AP + t*8 + lc;
                uint32_t bh[2] = {pk[0], pk[4]};
                const uint32_t* kl = Klo + (8*j + lr)*AP + t*8 + lc;
                uint32_t bl[2] = {kl[0], kl[4]};
                mma_bf16(s[j], ah, bh);
                mma_bf16(s[j], ah, bl);
                mma_bf16(s[j], al, bh);
            }
        }

        // scale + causal mask
        const int row0 = qs + warp*16 + lr, row1 = row0 + 8;
        #pragma unroll
        for (int j = 0; j < 8; j++) {
            int c0 = kb + 8*j + 2*lc, c1 = c0 + 1;
            s[j][0] = (c0 > row0) ? -1e30f : s[j][0]*INVSCALE;
            s[j][1] = (c1 > row0) ? -1e30f : s[j][1]*INVSCALE;
            s[j][2] = (c0 > row1) ? -1e30f : s[j][2]*INVSCALE;
            s[j][3] = (c1 > row1) ? -1e30f : s[j][3]*INVSCALE;
        }

        // online softmax (rows lr / lr+8), quad reductions
        float rm0 = -1e30f, rm1 = -1e30f;
        #pragma unroll
        for (int j = 0; j < 8; j++) {
            rm0 = fmaxf(rm0, fmaxf(s[j][0], s[j][1]));
            rm1 = fmaxf(rm1, fmaxf(s[j][2], s[j][3]));
        }
        rm0 = fmaxf(rm0, __shfl_xor_sync(0xffffffffu, rm0, 1));
        rm0 = fmaxf(rm0, __shfl_xor_sync(0xffffffffu, rm0, 2));
        rm1 = fmaxf(rm1, __shfl_xor_sync(0xffffffffu, rm1, 1));
        rm1 = fmaxf(rm1, __shfl_xor_sync(0xffffffffu, rm1, 2));
        float mn0 = fmaxf(m0, rm0), mn1 = fmaxf(m1, rm1);
        float cr0 = fexp(m0 - mn0), cr1 = fexp(m1 - mn1);
        l0s *= cr0; l1s *= cr1;
        #pragma unroll
        for (int j = 0; j < 8; j++) {
            o[j][0] *= cr0; o[j][1] *= cr0;
            o[j][2] *= cr1; o[j][3] *= cr1;
        }
        uint32_t phi[8][2], plo[8][2];
        float rs0 = 0.f, rs1 = 0.f;
        #pragma unroll
        for (int j = 0; j < 8; j++) {
            float p0 = fexp(s[j][0] - mn0), p1 = fexp(s[j][1] - mn0);
            float p2 = fexp(s[j][2] - mn1), p3 = fexp(s[j][3] - mn1);
            rs0 += p0 + p1; rs1 += p2 + p3;
            __nv_bfloat162 h01 = __floats2bfloat162_rn(p0, p1);
            __nv_bfloat162 h23 = __floats2bfloat162_rn(p2, p3);
            phi[j][0] = bf2_as_u32(h01);
            phi[j][1] = bf2_as_u32(h23);
            plo[j][0] = bf2_as_u32(__floats2bfloat162_rn(
                p0 - __low2float(h01), p1 - __high2float(h01)));
            plo[j][1] = bf2_as_u32(__floats2bfloat162_rn(
                p2 - __low2float(h23), p3 - __high2float(h23)));
        }
        rs0 += __shfl_xor_sync(0xffffffffu, rs0, 1);
        rs0 += __shfl_xor_sync(0xffffffffu, rs0, 2);
        rs1 += __shfl_xor_sync(0xffffffffu, rs1, 1);
        rs1 += __shfl_xor_sync(0xffffffffu, rs1, 2);
        l0s += rs0; l1s += rs1; m0 = mn0; m1 = mn1;

        // O += P V (3xBF16); P comes straight from registers (FA2 trick)
        #pragma unroll
        for (int t = 0; t < 4; t++) {
            uint32_t ah[4] = {phi[2*t][0], phi[2*t][1], phi[2*t+1][0], phi[2*t+1][1]};
            uint32_t al[4] = {plo[2*t][0], plo[2*t][1], plo[2*t+1][0], plo[2*t+1][1]};
            #pragma unroll
            for (int j = 0; j < 8; j++) {
                const uint32_t* pv = Vhi + (8*j + lr)*VP + t*8 + lc;
                uint32_t bh[2] = {pv[0], pv[4]};
                const uint32_t* pw = Vlo + (8*j + lr)*VP + t*8 + lc;
                uint32_t bl[2] = {pw[0], pw[4]};
                mma_bf16(o[j], ah, bh);
                mma_bf16(o[j], ah, bl);
                mma_bf16(o[j], al, bh);
            }
        }
    }

    float inv0 = 1.f / l0s, inv1 = 1.f / l1s;
    int grow0 = rowOff + qs + warp*16 + lr;
    #pragma unroll
    for (int j = 0; j < 8; j++) {
        int col = h*64 + 8*j + 2*lc;
        float2 v0 = {o[j][0]*inv0, o[j][1]*inv0};
        float2 v1 = {o[j][2]*inv1, o[j][3]*inv1};
        *(float2*)&out[(size_t)grow0*UP_ + col]     = v0;
        *(float2*)&out[(size_t)(grow0+8)*UP_ + col] = v1;
    }
}

extern "C" void kernel_launch(void* const* d_in, const int* in_sizes, int n_in,
                              void* d_out, int out_size)
{
    const float* h    = (const float*)d_in[0];
    const float* Wdkv = (const float*)d_in[2];  const float* bdkv = (const float*)d_in[3];
    const float* Wuk  = (const float*)d_in[4];  const float* buk  = (const float*)d_in[5];
    const float* Wuv  = (const float*)d_in[6];  const float* buv  = (const float*)d_in[7];
    const float* Wdq  = (const float*)d_in[8];  const float* bdq  = (const float*)d_in[9];
    const float* Wuq  = (const float*)d_in[10]; const float* buq  = (const float*)d_in[11];
    const float* Wqr  = (const float*)d_in[12]; const float* bqr  = (const float*)d_in[13];
    const float* Wkr  = (const float*)d_in[14]; const float* bkr  = (const float*)d_in[15];
    const float* Wfc  = (const float*)d_in[16]; const float* bfc  = (const float*)d_in[17];
    float* out = (float*)d_out;

    float *ckv, *cq, *krl, *kc, *vc, *qc, *qr, *ao;
    cudaGetSymbolAddress((void**)&ckv, g_ckv);
    cudaGetSymbolAddress((void**)&cq,  g_cq);
    cudaGetSymbolAddress((void**)&krl, g_krl);
    cudaGetSymbolAddress((void**)&kc,  g_kc);
    cudaGetSymbolAddress((void**)&vc,  g_vc);
    cudaGetSymbolAddress((void**)&qc,  g_qc);
    cudaGetSymbolAddress((void**)&qr,  g_qr);
    cudaGetSymbolAddress((void**)&ao,  g_ao);

    const int ATT_SMEM  = (4*64*AP + 2*64*VP)*(int)sizeof(uint32_t);  // 71680 B
    const int GEMM_SMEM = 2*4*PLANE*(int)sizeof(uint32_t);            // 81920 B
    cudaFuncSetAttribute(attn_mma,
                         cudaFuncAttributeMaxDynamicSharedMemorySize, ATT_SMEM);
    cudaFuncSetAttribute(gemm_bf16x3,
                         cudaFuncAttributeMaxDynamicSharedMemorySize, GEMM_SMEM);

    // projections (tensor-core 3xBF16)
    gemm_bf16x3<<<dim3(DOWN_/128, MROWS/128), 256, GEMM_SMEM>>>(h,   Wdkv, bdkv, ckv, MROWS, DOWN_, D_);
    gemm_bf16x3<<<dim3(DOWN_/128, MROWS/128), 256, GEMM_SMEM>>>(h,   Wdq,  bdq,  cq,  MROWS, DOWN_, D_);
    gemm_bias<<<dim3(1, MROWS/128), 256>>>(h, Wkr, bkr, krl, MROWS, RD_, D_);
    gemm_bf16x3<<<dim3(UP_/128,  MROWS/128), 256, GEMM_SMEM>>>(ckv, Wuk, buk, kc, MROWS, UP_,    DOWN_);
    gemm_bf16x3<<<dim3(UP_/128,  MROWS/128), 256, GEMM_SMEM>>>(ckv, Wuv, buv, vc, MROWS, UP_,    DOWN_);
    gemm_bf16x3<<<dim3(UP_/128,  MROWS/128), 256, GEMM_SMEM>>>(cq,  Wuq, buq, qc, MROWS, UP_,    DOWN_);
    gemm_bf16x3<<<dim3((RD_*H_)/128, MROWS/128), 256, GEMM_SMEM>>>(cq, Wqr, bqr, qr, MROWS, RD_*H_, DOWN_);

    // RoPE (negated angle)
    rope_kernel<<<MROWS, 256>>>(qr,  H_, RD_*H_);
    rope_kernel<<<MROWS, 32>>>(krl, 1,  RD_);

    // fused causal flash attention (mma bf16x3 + FMA-pipe exp)
    attn_mma<<<dim3(S_/64, H_, BS_), 128, ATT_SMEM>>>(qc, qr, kc, krl, vc, ao);

    // output projection
    gemm_bf16x3<<<dim3(D_/128, MROWS/128), 256, GEMM_SMEM>>>(ao, Wfc, bfc, out, MROWS, D_, UP_);
}